// round 8
// baseline (speedup 1.0000x reference)
#include <cuda_runtime.h>
#include <cstdint>
#include <cstddef>

// ---------------------------------------------------------------------------
// Quarter-K split, latency-optimized pipelined 2-layer GRU.
// 16 clusters x 8 CTAs x 832 threads (25 matvec warps + 1 aux warp).
// Thread (j, q4, b): j = warp (0-24), q4 = K-quarter, b = batch lane.
// Each thread accumulates NINE partial dots (3 gates x {Whh0.h0, Whh1.h1,
// Wih1.h0}) over its K-quarter using fma.f32x2 on ADJACENT k pairs from
// plain h0/h1 arrays (no interleave, no packing movs). Quarters combine via
// shfl.bfly(8,16). q4==0 lanes run both cells and push scalars to all CTAs.
// ONE cluster sync per iteration. Pipeline: at iter i, h0[p]=h0^(i),
// h1[p]=h1^(i-1), INB[p]=inputs_i.
// ---------------------------------------------------------------------------

#define HDIM   200
#define TSTEPS 1024
#define NB     8
#define NTHR   832
#define CLSZ   8
#define TITER  (TSTEPS + 2)
#define PITCH  204
#define HB     (NB*PITCH)      // 1632

typedef unsigned long long u64;

enum {
  O_WH0 = 0,                   // [3][25][200]
  O_WH1 = 15000,
  O_WM2 = 30000,               // W_ih1
  O_WFC = 45000,               // [4][200]
  O_WI0 = 45800,               // [3][25][8]
  O_B0  = 46400,               // r(25), z(25), nx(25), nh(25)
  O_B1  = 46500,
  O_BFC = 46600,               // [4]
  O_INB = 46608,               // [2][8][8]
  O_H0  = 46736,               // [2][8][PITCH]
  O_H1  = O_H0 + 2*HB,
  SMEM_F = O_H1 + 2*HB         // 53264 floats = 213056 B
};
#define SMEM_BYTES (SMEM_F*4)

#define FMA2(acc_, a_, b_) \
  asm("fma.rn.f32x2 %0, %1, %2, %0;" : "+l"(acc_) : "l"(a_), "l"(b_))
#define UNPK2(lo_, hi_, v_) \
  asm("mov.b64 {%0,%1}, %2;" : "=f"(lo_), "=f"(hi_) : "l"(v_))

__device__ __forceinline__ void cluster_sync() {
  asm volatile("barrier.cluster.arrive.aligned;" ::: "memory");
  asm volatile("barrier.cluster.wait.aligned;" ::: "memory");
}
__device__ __forceinline__ float sigmoid_f(float x) {
  return __fdividef(1.0f, 1.0f + __expf(-x));
}
__device__ __forceinline__ float tanh_f(float x) {
  float e = __expf(-2.0f * x);
  return __fdividef(2.0f, 1.0f + e) - 1.0f;
}

extern __shared__ float smem[];

__global__ void __launch_bounds__(NTHR, 1) __cluster_dims__(CLSZ, 1, 1)
gru2_kernel(const float* __restrict__ x,
            const float* __restrict__ W_ih0, const float* __restrict__ W_hh0,
            const float* __restrict__ b_ih0, const float* __restrict__ b_hh0,
            const float* __restrict__ W_ih1, const float* __restrict__ W_hh1,
            const float* __restrict__ b_ih1, const float* __restrict__ b_hh1,
            const float* __restrict__ W_fc,  const float* __restrict__ b_fc,
            float* __restrict__ out)
{
  const int tid = threadIdx.x;
  uint32_t rank;
  asm("mov.u32 %0, %%cluster_ctarank;" : "=r"(rank));
  const int g = blockIdx.x >> 3;
  uint32_t sb = (uint32_t)__cvta_generic_to_shared(smem);

  // ================= init =================
  {
    const float* srcs[3] = { W_hh0, W_hh1, W_ih1 };
    const int   dsts[3] = { O_WH0, O_WH1, O_WM2 };
    for (int m = 0; m < 3; m++) {
      const float4* s4 = (const float4*)srcs[m];
      float4* d4 = (float4*)(smem + dsts[m]);
      for (int f = tid; f < 3750; f += NTHR) {
        int row = f / 50, k4 = f % 50;
        int gt = row / 25, j = row % 25;
        d4[row*50 + k4] = s4[(size_t)(gt*HDIM + (int)rank*25 + j)*50 + k4];
      }
    }
  }
  for (int f = tid; f < 200; f += NTHR)
    ((float4*)(smem + O_WFC))[f] = ((const float4*)W_fc)[f];
  for (int f = tid; f < 600; f += NTHR) {
    int row = f >> 3, c = f & 7;
    int gt = row / 25, j = row % 25;
    smem[O_WI0 + f] = W_ih0[(size_t)(gt*HDIM + (int)rank*25 + j)*8 + c];
  }
  if (tid < 25) {
    int J = (int)rank*25 + tid;
    smem[O_B0 +      tid] = b_ih0[J]          + b_hh0[J];
    smem[O_B0 + 25 + tid] = b_ih0[HDIM + J]   + b_hh0[HDIM + J];
    smem[O_B0 + 50 + tid] = b_ih0[2*HDIM + J];
    smem[O_B0 + 75 + tid] = b_hh0[2*HDIM + J];
    smem[O_B1 +      tid] = b_ih1[J]          + b_hh1[J];
    smem[O_B1 + 25 + tid] = b_ih1[HDIM + J]   + b_hh1[HDIM + J];
    smem[O_B1 + 50 + tid] = b_ih1[2*HDIM + J];
    smem[O_B1 + 75 + tid] = b_hh1[2*HDIM + J];
  }
  if (tid < 4) smem[O_BFC + tid] = b_fc[tid];
  for (int f = tid; f < 2*HB; f += NTHR) { smem[O_H0 + f] = 0.f; smem[O_H1 + f] = 0.f; }
  if (tid < NB) {
    const float* xr = x + (size_t)(g*NB + tid) * TSTEPS * 8;
    // INB[0] = step-0 inputs; emotion into both parities
    float* i0 = smem + O_INB + tid*8;
    float* i1 = smem + O_INB + 64 + tid*8;
    i0[0] = 1.f; i0[1] = 1.f; i0[2] = 1.f; i0[3] = 1.f;
    i0[4] = xr[4]; i0[5] = xr[5]; i0[6] = xr[6]; i0[7] = xr[7];
    i1[4] = xr[4]; i1[5] = xr[5]; i1[6] = xr[6]; i1[7] = xr[7];
  }
  cluster_sync();

  // ---- per-thread constants ----
  const int j  = tid >> 5;              // warp = j (valid for tid<800)
  const int q4 = (tid >> 3) & 3;        // K quarter
  const int b  = tid & 7;               // batch lane
  const int gj = (int)rank*25 + j;
  const int kbeg   = (q4==0) ? 0 : (q4==1) ? 56 : (q4==2) ? 104 : 156;
  const int nchunk = (q4==0) ? 14 : (q4==1) ? 12 : (q4==2) ? 13 : 11;
  const float* w0r = smem + O_WH0 + (     j)*200 + kbeg;
  const float* w0z = smem + O_WH0 + (25 + j)*200 + kbeg;
  const float* w0n = smem + O_WH0 + (50 + j)*200 + kbeg;
  const float* w1r = smem + O_WH1 + (     j)*200 + kbeg;
  const float* w1z = smem + O_WH1 + (25 + j)*200 + kbeg;
  const float* w1n = smem + O_WH1 + (50 + j)*200 + kbeg;
  const float* w2r = smem + O_WM2 + (     j)*200 + kbeg;
  const float* w2z = smem + O_WM2 + (25 + j)*200 + kbeg;
  const float* w2n = smem + O_WM2 + (50 + j)*200 + kbeg;

  float4 xnext = make_float4(0.f, 0.f, 0.f, 0.f);

  for (int i = 0; i < TITER; i++) {
    const int p = i & 1, qq = p ^ 1;

    if (tid < 800 && i <= TSTEPS) {
      // ================= matvec: nine partial dots over K-quarter ========
      const float* h0p = smem + O_H0 + p*HB + b*PITCH + kbeg;
      const float* h1p = smem + O_H1 + p*HB + b*PITCH + kbeg;
      u64 a0=0,a1=0,a2=0,a3=0,a4=0,a5=0,a6=0,a7=0,a8=0;
      #pragma unroll 2
      for (int c = 0; c < nchunk; c++) {
        const int kk = c*4;
        ulonglong2 H0 = *(const ulonglong2*)(h0p + kk);
        ulonglong2 H1 = *(const ulonglong2*)(h1p + kk);
        ulonglong2 W;
        W = *(const ulonglong2*)(w0r + kk); FMA2(a0, W.x, H0.x); FMA2(a0, W.y, H0.y);
        W = *(const ulonglong2*)(w0z + kk); FMA2(a1, W.x, H0.x); FMA2(a1, W.y, H0.y);
        W = *(const ulonglong2*)(w0n + kk); FMA2(a2, W.x, H0.x); FMA2(a2, W.y, H0.y);
        W = *(const ulonglong2*)(w1r + kk); FMA2(a3, W.x, H1.x); FMA2(a3, W.y, H1.y);
        W = *(const ulonglong2*)(w1z + kk); FMA2(a4, W.x, H1.x); FMA2(a4, W.y, H1.y);
        W = *(const ulonglong2*)(w1n + kk); FMA2(a5, W.x, H1.x); FMA2(a5, W.y, H1.y);
        W = *(const ulonglong2*)(w2r + kk); FMA2(a6, W.x, H0.x); FMA2(a6, W.y, H0.y);
        W = *(const ulonglong2*)(w2z + kk); FMA2(a7, W.x, H0.x); FMA2(a7, W.y, H0.y);
        W = *(const ulonglong2*)(w2n + kk); FMA2(a8, W.x, H0.x); FMA2(a8, W.y, H0.y);
      }
      float d0,d1,d2,d3,d4,d5,d6,d7,d8;
      { float lo, hi;
        UNPK2(lo, hi, a0); d0 = lo + hi;
        UNPK2(lo, hi, a1); d1 = lo + hi;
        UNPK2(lo, hi, a2); d2 = lo + hi;
        UNPK2(lo, hi, a3); d3 = lo + hi;
        UNPK2(lo, hi, a4); d4 = lo + hi;
        UNPK2(lo, hi, a5); d5 = lo + hi;
        UNPK2(lo, hi, a6); d6 = lo + hi;
        UNPK2(lo, hi, a7); d7 = lo + hi;
        UNPK2(lo, hi, a8); d8 = lo + hi;
      }
      // combine K-quarters: partners at lane^8, lane^16
      d0 += __shfl_xor_sync(0xffffffffu, d0, 8);
      d1 += __shfl_xor_sync(0xffffffffu, d1, 8);
      d2 += __shfl_xor_sync(0xffffffffu, d2, 8);
      d3 += __shfl_xor_sync(0xffffffffu, d3, 8);
      d4 += __shfl_xor_sync(0xffffffffu, d4, 8);
      d5 += __shfl_xor_sync(0xffffffffu, d5, 8);
      d6 += __shfl_xor_sync(0xffffffffu, d6, 8);
      d7 += __shfl_xor_sync(0xffffffffu, d7, 8);
      d8 += __shfl_xor_sync(0xffffffffu, d8, 8);
      d0 += __shfl_xor_sync(0xffffffffu, d0, 16);
      d1 += __shfl_xor_sync(0xffffffffu, d1, 16);
      d2 += __shfl_xor_sync(0xffffffffu, d2, 16);
      d3 += __shfl_xor_sync(0xffffffffu, d3, 16);
      d4 += __shfl_xor_sync(0xffffffffu, d4, 16);
      d5 += __shfl_xor_sync(0xffffffffu, d5, 16);
      d6 += __shfl_xor_sync(0xffffffffu, d6, 16);
      d7 += __shfl_xor_sync(0xffffffffu, d7, 16);
      d8 += __shfl_xor_sync(0xffffffffu, d8, 16);

      // ================= cells + push (q4 == 0 lanes) =================
      if (q4 == 0) {
        float h0new = 0.f, h1new = 0.f;
        if (i < TSTEPS) {
          float xr = smem[O_B0 + j], xz = smem[O_B0 + 25 + j], xn = smem[O_B0 + 50 + j];
          const float* ib = smem + O_INB + p*64 + b*8;
          #pragma unroll
          for (int c = 0; c < 8; c++) {
            float ic = ib[c];
            xr = fmaf(smem[O_WI0 +       j*8 + c], ic, xr);
            xz = fmaf(smem[O_WI0 + 200 + j*8 + c], ic, xz);
            xn = fmaf(smem[O_WI0 + 400 + j*8 + c], ic, xn);
          }
          float r = sigmoid_f(xr + d0);
          float z = sigmoid_f(xz + d1);
          float n = tanh_f(xn + r * (d2 + smem[O_B0 + 75 + j]));
          float h_o = smem[O_H0 + p*HB + b*PITCH + gj];
          h0new = n + z * (h_o - n);
        }
        if (i >= 1) {
          float r = sigmoid_f(d6 + d3 + smem[O_B1 + j]);
          float z = sigmoid_f(d7 + d4 + smem[O_B1 + 25 + j]);
          float n = tanh_f(d8 + smem[O_B1 + 50 + j] +
                           r * (d5 + smem[O_B1 + 75 + j]));
          float h_o = smem[O_H1 + p*HB + b*PITCH + gj];
          h1new = n + z * (h_o - n);
        }
        uint32_t la0 = sb + (uint32_t)(O_H0 + qq*HB + b*PITCH + gj) * 4;
        uint32_t la1 = sb + (uint32_t)(O_H1 + qq*HB + b*PITCH + gj) * 4;
        #pragma unroll
        for (int rr = 0; rr < CLSZ; rr++) {
          uint32_t ra;
          asm("mapa.shared::cluster.u32 %0, %1, %2;" : "=r"(ra) : "r"(la0), "r"(rr));
          asm volatile("st.shared::cluster.f32 [%0], %1;" :: "r"(ra), "f"(h0new) : "memory");
          asm("mapa.shared::cluster.u32 %0, %1, %2;" : "=r"(ra) : "r"(la1), "r"(rr));
          asm volatile("st.shared::cluster.f32 [%0], %1;" :: "r"(ra), "f"(h1new) : "memory");
        }
      }
    } else if (tid >= 800) {
      const int lane = tid - 800;
      if (lane < 8) {
        // prefetch x[b, i, 0:4] (inputs for step i+1)
        if (i < TSTEPS)
          xnext = *(const float4*)(x + ((size_t)(g*NB + lane) * TSTEPS + i) * 8);
        // stage INB[qq] for step i+1
        if (i < TSTEPS) {
          float* ib = smem + O_INB + qq*64 + lane*8;
          ib[0] = xnext.x; ib[1] = xnext.y; ib[2] = xnext.z; ib[3] = xnext.w;
        }
      } else if (lane < 12 && i >= 2) {
        // FC: out_{i-2} = tanh(Wfc . h1^(i-1));  4 (o,b) pairs per CTA
        int pidx = (int)rank*4 + (lane - 8);
        int o = pidx >> 3, fb = pidx & 7;
        const float* wf = smem + O_WFC + o*HDIM;
        const float* hv = smem + O_H1 + p*HB + fb*PITCH;
        float s0 = 0.f, s1 = 0.f, s2 = 0.f, s3 = 0.f;
        #pragma unroll 10
        for (int k = 0; k < HDIM; k += 4) {
          float4 W = *(const float4*)(wf + k);
          float4 H = *(const float4*)(hv + k);
          s0 = fmaf(W.x, H.x, s0); s1 = fmaf(W.y, H.y, s1);
          s2 = fmaf(W.z, H.z, s2); s3 = fmaf(W.w, H.w, s3);
        }
        float v = tanh_f(s0 + s1 + s2 + s3 + smem[O_BFC + o]);
        out[((size_t)(g*NB + fb) * TSTEPS + (i-2)) * 4 + o] = v;
      }
    }
    cluster_sync();
  }
}

extern "C" void kernel_launch(void* const* d_in, const int* in_sizes, int n_in,
                              void* d_out, int out_size) {
  (void)in_sizes; (void)n_in; (void)out_size;
  const float* x     = (const float*)d_in[0];
  const float* W_ih0 = (const float*)d_in[1];
  const float* W_hh0 = (const float*)d_in[2];
  const float* b_ih0 = (const float*)d_in[3];
  const float* b_hh0 = (const float*)d_in[4];
  const float* W_ih1 = (const float*)d_in[5];
  const float* W_hh1 = (const float*)d_in[6];
  const float* b_ih1 = (const float*)d_in[7];
  const float* b_hh1 = (const float*)d_in[8];
  const float* W_fc  = (const float*)d_in[9];
  const float* b_fc  = (const float*)d_in[10];

  cudaFuncSetAttribute(gru2_kernel,
                       cudaFuncAttributeMaxDynamicSharedMemorySize, SMEM_BYTES);
  gru2_kernel<<<128, NTHR, SMEM_BYTES>>>(x, W_ih0, W_hh0, b_ih0, b_hh0,
                                         W_ih1, W_hh1, b_ih1, b_hh1,
                                         W_fc, b_fc, (float*)d_out);
}

// round 9
// speedup vs baseline: 1.3618x; 1.3618x over previous
#include <cuda_runtime.h>
#include <cstdint>
#include <cstddef>

// ---------------------------------------------------------------------------
// Layer-sequential 2-layer GRU — NO clusters, NO cross-SM sync.
//   K1: 128 CTAs x 832 thr. CTA = one batch element; layer-0 recurrence over
//       all 1024 steps. W_hh0 in registers (thread (j,q4) owns 3 gate
//       quarter-rows = 75 u64). h0 ring in local smem; ONE bar.sync/step.
//       Writes h0_post[t] to __device__ scratch.
//   K2: 128 CTAs x 800 thr, free-running (no barriers): gx1[b,t,:] =
//       W_ih1 . h0_post[b,t]  (W_ih1 in registers, h0 via LDG).
//   K3: 128 CTAs x 832 thr. Layer-1 recurrence (W_hh1 in registers, gx1
//       prefetched 2 steps ahead from gmem) + FC output in aux warp.
// ---------------------------------------------------------------------------

#define TSTEPS 1024
#define HDIM   200
#define NBATCH 128

typedef unsigned long long u64;

__device__ float g_h0[(size_t)NBATCH * TSTEPS * HDIM];    // 105 MB
__device__ float g_gx1[(size_t)NBATCH * TSTEPS * 600];    // 315 MB

#define FMA2(acc_, a_, b_) \
  asm("fma.rn.f32x2 %0, %1, %2, %0;" : "+l"(acc_) : "l"(a_), "l"(b_))
#define UNPK2(lo_, hi_, v_) \
  asm("mov.b64 {%0,%1}, %2;" : "=f"(lo_), "=f"(hi_) : "l"(v_))

__device__ __forceinline__ float sigmoid_f(float x) {
  return __fdividef(1.0f, 1.0f + __expf(-x));
}
__device__ __forceinline__ float tanh_f(float x) {
  float e = __expf(-2.0f * x);
  return __fdividef(2.0f, 1.0f + e) - 1.0f;
}

// ============================ K1: layer 0 ==================================
__global__ void __launch_bounds__(832, 1)
k1_layer0(const float* __restrict__ x,
          const float* __restrict__ W_ih0, const float* __restrict__ W_hh0,
          const float* __restrict__ b_ih0, const float* __restrict__ b_hh0)
{
  __shared__ float sh[2*208];     // h0 ring
  __shared__ float sI[2*8];       // input ring {tf0..3, em0..3}
  __shared__ float sW[4800];      // W_ih0 [600][8]
  __shared__ float sB[800];       // biases: r_comb, z_comb, n_ih, n_hh

  const int tid = threadIdx.x;
  const int b = blockIdx.x;

  for (int f = tid; f < 4800; f += 832) sW[f] = W_ih0[f];
  for (int f = tid; f < 200; f += 832) {
    sB[f]       = b_ih0[f]       + b_hh0[f];
    sB[200 + f] = b_ih0[200 + f] + b_hh0[200 + f];
    sB[400 + f] = b_ih0[400 + f];
    sB[600 + f] = b_hh0[400 + f];
  }
  if (tid < 208) { sh[tid] = 0.f; sh[208 + tid] = 0.f; }

  const int j = tid >> 2, q4 = tid & 3;
  u64 w[75];
  if (tid < 800) {
    #pragma unroll
    for (int g = 0; g < 3; g++) {
      const u64* src = (const u64*)(W_hh0 + ((size_t)(g*200 + j))*200 + q4*50);
      #pragma unroll
      for (int c = 0; c < 25; c++) w[g*25 + c] = src[c];
    }
  }
  float4 xnext = make_float4(0.f, 0.f, 0.f, 0.f);
  if (tid == 800) {
    float4 em = *(const float4*)(x + (size_t)b*TSTEPS*8 + 4);
    sI[0] = 1.f; sI[1] = 1.f; sI[2] = 1.f; sI[3] = 1.f;
    sI[4] = em.x; sI[5] = em.y; sI[6] = em.z; sI[7] = em.w;
    sI[12] = em.x; sI[13] = em.y; sI[14] = em.z; sI[15] = em.w;
    xnext = *(const float4*)(x + (size_t)b*TSTEPS*8);   // tf for step 1
  }
  __syncthreads();

  float* hout = g_h0 + (size_t)b*TSTEPS*HDIM;

  for (int t = 0; t < TSTEPS; t++) {
    const int p = t & 1, q = p ^ 1;
    if (tid < 800) {
      const u64* hq = (const u64*)(sh + p*208 + q4*50);
      u64 a0 = 0, a1 = 0, a2 = 0;
      #pragma unroll
      for (int c = 0; c < 25; c++) {
        u64 H = hq[c];
        FMA2(a0, w[c],      H);
        FMA2(a1, w[25 + c], H);
        FMA2(a2, w[50 + c], H);
      }
      float d0, d1, d2, lo, hi;
      UNPK2(lo, hi, a0); d0 = lo + hi;
      UNPK2(lo, hi, a1); d1 = lo + hi;
      UNPK2(lo, hi, a2); d2 = lo + hi;
      d0 += __shfl_xor_sync(0xffffffffu, d0, 1);
      d0 += __shfl_xor_sync(0xffffffffu, d0, 2);
      d1 += __shfl_xor_sync(0xffffffffu, d1, 1);
      d1 += __shfl_xor_sync(0xffffffffu, d1, 2);
      d2 += __shfl_xor_sync(0xffffffffu, d2, 1);
      d2 += __shfl_xor_sync(0xffffffffu, d2, 2);
      if (q4 == 0) {
        const float* ib = sI + p*8;
        float xr = sB[j], xz = sB[200 + j], xn = sB[400 + j];
        #pragma unroll
        for (int c = 0; c < 8; c++) {
          float ic = ib[c];
          xr = fmaf(sW[        j*8 + c], ic, xr);
          xz = fmaf(sW[(200 + j)*8 + c], ic, xz);
          xn = fmaf(sW[(400 + j)*8 + c], ic, xn);
        }
        float r = sigmoid_f(xr + d0);
        float z = sigmoid_f(xz + d1);
        float n = tanh_f(xn + r * (d2 + sB[600 + j]));
        float ho = sh[p*208 + j];
        float hn = n + z * (ho - n);
        sh[q*208 + j] = hn;
        hout[(size_t)t*HDIM + j] = hn;
      }
    } else if (tid == 800) {
      float* ib = sI + q*8;     // tf for step t+1 = x[b, t, 0:4]
      ib[0] = xnext.x; ib[1] = xnext.y; ib[2] = xnext.z; ib[3] = xnext.w;
      if (t + 1 < TSTEPS)
        xnext = *(const float4*)(x + ((size_t)b*TSTEPS + (t + 1))*8);
    }
    __syncthreads();
  }
}

// ============================ K2: gx1 GEMM =================================
__global__ void __launch_bounds__(800, 1)
k2_gx1(const float* __restrict__ W_ih1)
{
  const int tid = threadIdx.x;
  const int b = blockIdx.x;
  const int j = tid >> 2, q4 = tid & 3;

  u64 w[75];
  #pragma unroll
  for (int g = 0; g < 3; g++) {
    const u64* src = (const u64*)(W_ih1 + ((size_t)(g*200 + j))*200 + q4*50);
    #pragma unroll
    for (int c = 0; c < 25; c++) w[g*25 + c] = src[c];
  }
  const float* hin = g_h0 + (size_t)b*TSTEPS*HDIM;
  float* gout = g_gx1 + (size_t)b*TSTEPS*600;

  for (int t = 0; t < TSTEPS; t++) {
    const u64* hq = (const u64*)(hin + (size_t)t*HDIM + q4*50);
    u64 a0 = 0, a1 = 0, a2 = 0;
    #pragma unroll
    for (int c = 0; c < 25; c++) {
      u64 H = __ldg(hq + c);
      FMA2(a0, w[c],      H);
      FMA2(a1, w[25 + c], H);
      FMA2(a2, w[50 + c], H);
    }
    float d0, d1, d2, lo, hi;
    UNPK2(lo, hi, a0); d0 = lo + hi;
    UNPK2(lo, hi, a1); d1 = lo + hi;
    UNPK2(lo, hi, a2); d2 = lo + hi;
    d0 += __shfl_xor_sync(0xffffffffu, d0, 1);
    d0 += __shfl_xor_sync(0xffffffffu, d0, 2);
    d1 += __shfl_xor_sync(0xffffffffu, d1, 1);
    d1 += __shfl_xor_sync(0xffffffffu, d1, 2);
    d2 += __shfl_xor_sync(0xffffffffu, d2, 1);
    d2 += __shfl_xor_sync(0xffffffffu, d2, 2);
    if (q4 == 0) {
      gout[(size_t)t*600 +       j] = d0;
      gout[(size_t)t*600 + 200 + j] = d1;
      gout[(size_t)t*600 + 400 + j] = d2;
    }
  }
}

// ============================ K3: layer 1 + FC =============================
__global__ void __launch_bounds__(832, 1)
k3_layer1(const float* __restrict__ W_hh1,
          const float* __restrict__ b_ih1, const float* __restrict__ b_hh1,
          const float* __restrict__ W_fc,  const float* __restrict__ b_fc,
          float* __restrict__ out)
{
  __shared__ float sh[2*208];     // h1 ring
  __shared__ float sB[800];
  __shared__ float sF[800];       // W_fc [4][200]
  __shared__ float sbf[4];

  const int tid = threadIdx.x;
  const int b = blockIdx.x;

  for (int f = tid; f < 800; f += 832) sF[f] = W_fc[f];
  for (int f = tid; f < 200; f += 832) {
    sB[f]       = b_ih1[f]       + b_hh1[f];
    sB[200 + f] = b_ih1[200 + f] + b_hh1[200 + f];
    sB[400 + f] = b_ih1[400 + f];
    sB[600 + f] = b_hh1[400 + f];
  }
  if (tid < 208) { sh[tid] = 0.f; sh[208 + tid] = 0.f; }
  if (tid < 4) sbf[tid] = b_fc[tid];

  const int j = tid >> 2, q4 = tid & 3;
  u64 w[75];
  if (tid < 800) {
    #pragma unroll
    for (int g = 0; g < 3; g++) {
      const u64* src = (const u64*)(W_hh1 + ((size_t)(g*200 + j))*200 + q4*50);
      #pragma unroll
      for (int c = 0; c < 25; c++) w[g*25 + c] = src[c];
    }
  }
  const float* gin = g_gx1 + (size_t)b*TSTEPS*600;
  // gx1 prefetch ring: u* for even t, v* for odd t (2-step depth)
  float u0 = 0.f, u1 = 0.f, u2 = 0.f, v0 = 0.f, v1 = 0.f, v2 = 0.f;
  const bool cell = (tid < 800) && (q4 == 0);
  if (cell) {
    u0 = gin[j];        u1 = gin[200 + j];  u2 = gin[400 + j];   // t=0
    v0 = gin[600 + j];  v1 = gin[800 + j];  v2 = gin[1000 + j];  // t=1
  }
  __syncthreads();

  for (int t = 0; t < TSTEPS; t++) {
    const int p = t & 1, q = p ^ 1;
    if (tid < 800) {
      const u64* hq = (const u64*)(sh + p*208 + q4*50);
      u64 a0 = 0, a1 = 0, a2 = 0;
      #pragma unroll
      for (int c = 0; c < 25; c++) {
        u64 H = hq[c];
        FMA2(a0, w[c],      H);
        FMA2(a1, w[25 + c], H);
        FMA2(a2, w[50 + c], H);
      }
      float d0, d1, d2, lo, hi;
      UNPK2(lo, hi, a0); d0 = lo + hi;
      UNPK2(lo, hi, a1); d1 = lo + hi;
      UNPK2(lo, hi, a2); d2 = lo + hi;
      d0 += __shfl_xor_sync(0xffffffffu, d0, 1);
      d0 += __shfl_xor_sync(0xffffffffu, d0, 2);
      d1 += __shfl_xor_sync(0xffffffffu, d1, 1);
      d1 += __shfl_xor_sync(0xffffffffu, d1, 2);
      d2 += __shfl_xor_sync(0xffffffffu, d2, 1);
      d2 += __shfl_xor_sync(0xffffffffu, d2, 2);
      if (cell) {
        float gr = p ? v0 : u0;
        float gz = p ? v1 : u1;
        float gn = p ? v2 : u2;
        float r = sigmoid_f(gr + d0 + sB[j]);
        float z = sigmoid_f(gz + d1 + sB[200 + j]);
        float n = tanh_f(gn + sB[400 + j] + r * (d2 + sB[600 + j]));
        float ho = sh[p*208 + j];
        float hn = n + z * (ho - n);
        sh[q*208 + j] = hn;
        if (t + 2 < TSTEPS) {
          const float* gp = gin + (size_t)(t + 2)*600;
          if (p) { v0 = gp[j]; v1 = gp[200 + j]; v2 = gp[400 + j]; }
          else   { u0 = gp[j]; u1 = gp[200 + j]; u2 = gp[400 + j]; }
        }
      }
    } else if (tid >= 800 && tid < 804 && t > 0) {
      // FC: out[t-1] = tanh(W_fc . h1_post[t-1]) ; h1_post[t-1] = sh[p]
      const int o = tid - 800;
      const float* wf = sF + o*200;
      const float* hv = sh + p*208;
      float s0 = 0.f, s1 = 0.f, s2 = 0.f, s3 = 0.f;
      #pragma unroll 10
      for (int k = 0; k < 200; k += 4) {
        s0 = fmaf(wf[k],     hv[k],     s0);
        s1 = fmaf(wf[k + 1], hv[k + 1], s1);
        s2 = fmaf(wf[k + 2], hv[k + 2], s2);
        s3 = fmaf(wf[k + 3], hv[k + 3], s3);
      }
      float v = tanh_f(s0 + s1 + s2 + s3 + sbf[o]);
      out[((size_t)b*TSTEPS + (t - 1))*4 + o] = v;
    }
    __syncthreads();
  }
  // final output t = 1023: h1_post[1023] sits in parity (1024 & 1) = 0
  if (tid >= 800 && tid < 804) {
    const int o = tid - 800;
    const float* wf = sF + o*200;
    const float* hv = sh;
    float s0 = 0.f, s1 = 0.f, s2 = 0.f, s3 = 0.f;
    #pragma unroll 10
    for (int k = 0; k < 200; k += 4) {
      s0 = fmaf(wf[k],     hv[k],     s0);
      s1 = fmaf(wf[k + 1], hv[k + 1], s1);
      s2 = fmaf(wf[k + 2], hv[k + 2], s2);
      s3 = fmaf(wf[k + 3], hv[k + 3], s3);
    }
    float v = tanh_f(s0 + s1 + s2 + s3 + sbf[o]);
    out[((size_t)b*TSTEPS + (TSTEPS - 1))*4 + o] = v;
  }
}

// ============================ launch =======================================
extern "C" void kernel_launch(void* const* d_in, const int* in_sizes, int n_in,
                              void* d_out, int out_size) {
  (void)in_sizes; (void)n_in; (void)out_size;
  const float* x     = (const float*)d_in[0];
  const float* W_ih0 = (const float*)d_in[1];
  const float* W_hh0 = (const float*)d_in[2];
  const float* b_ih0 = (const float*)d_in[3];
  const float* b_hh0 = (const float*)d_in[4];
  const float* W_ih1 = (const float*)d_in[5];
  const float* W_hh1 = (const float*)d_in[6];
  const float* b_ih1 = (const float*)d_in[7];
  const float* b_hh1 = (const float*)d_in[8];
  const float* W_fc  = (const float*)d_in[9];
  const float* b_fc  = (const float*)d_in[10];

  k1_layer0<<<NBATCH, 832>>>(x, W_ih0, W_hh0, b_ih0, b_hh0);
  k2_gx1<<<NBATCH, 800>>>(W_ih1);
  k3_layer1<<<NBATCH, 832>>>(W_hh1, b_ih1, b_hh1, W_fc, b_fc, (float*)d_out);
}